// round 13
// baseline (speedup 1.0000x reference)
#include <cuda_runtime.h>
#include <cuda_bf16.h>
#include <cstdint>

#define N_AG  1024
#define HID   128
#define KDIM  2048
#define OUTD  128
#define CELLS 1024
#define NKS   16            // split-K slices (128 k each)

// ---- scratch (device globals; no allocs allowed) ----
__device__ float g_part[NKS * N_AG * OUTD];    // 8 MB split-K partials
__device__ int   g_ent[N_AG * CELLS];          // winner entries (j<<4)|blk
__device__ int   g_cnt[N_AG];

__device__ __forceinline__ uint32_t smem_u32(const void* p) {
    uint32_t a;
    asm("{ .reg .u64 t; cvta.to.shared.u64 t, %1; cvt.u32.u64 %0, t; }" : "=r"(a) : "l"(p));
    return a;
}
__device__ __forceinline__ void griddep_wait() {
    asm volatile("griddepcontrol.wait;" ::: "memory");
}
__device__ __forceinline__ void ldsm_x4(uint32_t& r0, uint32_t& r1, uint32_t& r2, uint32_t& r3,
                                        uint32_t addr) {
    asm volatile("ldmatrix.sync.aligned.m8n8.x4.shared.b16 {%0,%1,%2,%3}, [%4];"
                 : "=r"(r0), "=r"(r1), "=r"(r2), "=r"(r3) : "r"(addr));
}
__device__ __forceinline__ void mma16816(float* c, const uint32_t* a, const uint32_t* b) {
    asm volatile("mma.sync.aligned.m16n8k16.row.col.f32.bf16.bf16.f32 "
                 "{%0,%1,%2,%3}, {%4,%5,%6,%7}, {%8,%9}, {%0,%1,%2,%3};"
                 : "+f"(c[0]), "+f"(c[1]), "+f"(c[2]), "+f"(c[3])
                 : "r"(a[0]), "r"(a[1]), "r"(a[2]), "r"(a[3]), "r"(b[0]), "r"(b[1]));
}

// ===================== kernel 1: scatter (winner compaction) =================
// One CTA per ego; set-semantics (max j wins == XLA scatter update order).
__global__ void __launch_bounds__(256) scatter_kernel(const float* __restrict__ obs2) {
    __shared__ int w[CELLS];
    __shared__ int s_cnt;
    const int i = blockIdx.x;
    const int t = threadIdx.x;     // 256

    for (int c = t; c < CELLS; c += 256) w[c] = -1;
    if (t == 0) s_cnt = 0;
    const float2 oi = ((const float2*)obs2)[i];
    __syncthreads();

    if (oi.x != oi.x) {            // ego NaN -> no neighbors
        if (t == 0) g_cnt[i] = 0;
        return;
    }
    for (int j = t; j < N_AG; j += 256) {
        if (j == i) continue;
        float2 oj = ((const float2*)obs2)[j];
        if (oj.x != oj.x) continue;
        float ox = (oj.x - oi.x) * 4.0f + 16.0f;   // exact pow2 scale
        float oy = (oj.y - oi.y) * 4.0f + 16.0f;
        if (ox >= 0.0f && ox < 32.0f && oy >= 0.0f && oy < 32.0f)
            atomicMax(&w[((int)ox) * 32 + (int)oy], j);
    }
    __syncthreads();

    int* ent = g_ent + (i << 10);
    for (int c = t; c < CELLS; c += 256) {
        int j = w[c];
        if (j >= 0) {
            int blk = ((c >> 8) << 2) | ((c & 31) >> 3);   // gi*4+gj
            int p = atomicAdd(&s_cnt, 1);
            ent[p] = (j << 4) | blk;
        }
    }
    __syncthreads();
    if (t == 0) g_cnt[i] = s_cnt;
    // implicit launch_dependents at exit -> writes visible to flatgemm
}

// ===================== kernel 2: flat build + mma.sync GEMM ==================
// grid (8 m-tiles, 16 k-slices), 256 thr.
// k-slice ksl covers k = h*16+blk for h in [8ksl, 8ksl+8) -> k0 = 128*ksl,
// CONTIGUOUS in W's natural layout (no transpose needed!).
// part[ksl][m][n] = sum_k flat[m][k] * W[n][k] over the slice, 3 bf16 passes.
#define LDS   136
#define TILE  (128 * LDS)                      // bf16 elements per tile
#define FLDS  132                              // fp32 flat row stride
#define SMEM_DYN (4 * TILE * 2 + 128 * FLDS * 4)   // 206848 B

__global__ void __launch_bounds__(256, 1) flatgemm_kernel(const float* __restrict__ Hs,
                                                          const float* __restrict__ W) {
    extern __shared__ __nv_bfloat16 sm[];
    __nv_bfloat16* sFh = sm;                   // flat hi
    __nv_bfloat16* sFl = sm + TILE;            // flat lo
    __nv_bfloat16* sWh = sm + 2 * TILE;        // W hi
    __nv_bfloat16* sWl = sm + 3 * TILE;        // W lo
    float* sFlat = (float*)(sm + 4 * TILE);    // [128][FLDS] fp32

    const int t   = threadIdx.x;
    const int w   = t >> 5;
    const int l   = t & 31;
    const int m0  = blockIdx.x << 7;
    const int ksl = blockIdx.y;
    const int k0  = ksl << 7;                  // W column offset
    const int h0  = ksl << 3;                  // hidden h offset
    const int wm  = (w >> 2) * 64;
    const int wn  = (w & 3) * 32;

    // ---- W slice convert (independent of scatter): W[n][k0..k0+128) ----
#pragma unroll
    for (int q = t; q < 4096; q += 256) {      // 128 rows x 32 float4
        int r = q >> 5, c = q & 31;
        float4 v = *(const float4*)(W + r * KDIM + k0 + c * 4);
        __align__(8) __nv_bfloat16 hi[4];
        __align__(8) __nv_bfloat16 lo[4];
        hi[0] = __float2bfloat16(v.x); lo[0] = __float2bfloat16(v.x - __bfloat162float(hi[0]));
        hi[1] = __float2bfloat16(v.y); lo[1] = __float2bfloat16(v.y - __bfloat162float(hi[1]));
        hi[2] = __float2bfloat16(v.z); lo[2] = __float2bfloat16(v.z - __bfloat162float(hi[2]));
        hi[3] = __float2bfloat16(v.w); lo[3] = __float2bfloat16(v.w - __bfloat162float(hi[3]));
        *(uint2*)(sWh + r * LDS + c * 4) = *(const uint2*)&hi[0];
        *(uint2*)(sWl + r * LDS + c * 4) = *(const uint2*)&lo[0];
    }
    // zero flat staging
    for (int q = t; q < 128 * FLDS; q += 256) sFlat[q] = 0.0f;
    __syncthreads();

    griddep_wait();                            // scatter results now visible

    // ---- flat build: 2 threads per ego, 4 h-values each ----
    {
        const int i = t >> 1, half = t & 1;
        const int cnt = g_cnt[m0 + i];
        const int* ent = g_ent + ((m0 + i) << 10);
        float* dst = sFlat + i * FLDS;
        for (int e = 0; e < cnt; e++) {
            int en  = ent[e];
            int j   = en >> 4;
            int blk = en & 15;
            float4 hv = *(const float4*)(Hs + j * HID + h0 + half * 4);
            // k_local = (h - h0)*16 + blk
            dst[(half * 4 + 0) * 16 + blk] += hv.x;
            dst[(half * 4 + 1) * 16 + blk] += hv.y;
            dst[(half * 4 + 2) * 16 + blk] += hv.z;
            dst[(half * 4 + 3) * 16 + blk] += hv.w;
        }
    }
    __syncthreads();

    // ---- flat fp32 -> bf16 hi/lo ----
#pragma unroll
    for (int q = t; q < 4096; q += 256) {      // 128 rows x 32 float4
        int r = q >> 5, c = q & 31;
        float4 v = *(const float4*)(sFlat + r * FLDS + c * 4);
        __align__(8) __nv_bfloat16 hi[4];
        __align__(8) __nv_bfloat16 lo[4];
        hi[0] = __float2bfloat16(v.x); lo[0] = __float2bfloat16(v.x - __bfloat162float(hi[0]));
        hi[1] = __float2bfloat16(v.y); lo[1] = __float2bfloat16(v.y - __bfloat162float(hi[1]));
        hi[2] = __float2bfloat16(v.z); lo[2] = __float2bfloat16(v.z - __bfloat162float(hi[2]));
        hi[3] = __float2bfloat16(v.w); lo[3] = __float2bfloat16(v.w - __bfloat162float(hi[3]));
        *(uint2*)(sFh + r * LDS + c * 4) = *(const uint2*)&hi[0];
        *(uint2*)(sFl + r * LDS + c * 4) = *(const uint2*)&lo[0];
    }
    __syncthreads();

    // ---- 3-pass mma: Fh*Wh + Fh*Wl + Fl*Wh ----
    float acc[4][4][4];
#pragma unroll
    for (int mi = 0; mi < 4; mi++)
#pragma unroll
        for (int ni = 0; ni < 4; ni++)
#pragma unroll
            for (int q = 0; q < 4; q++) acc[mi][ni][q] = 0.0f;

    const int aRow = wm + (l & 15);
    const int aCol = (l >> 4) * 8;
    const int bRow = wn + ((l >> 4) * 8) + (l & 7);
    const int bCol = ((l >> 3) & 1) * 8;

    const uint32_t aHB = smem_u32(sFh + aRow * LDS + aCol);
    const uint32_t aLB = smem_u32(sFl + aRow * LDS + aCol);
    const uint32_t bHB = smem_u32(sWh + bRow * LDS + bCol);
    const uint32_t bLB = smem_u32(sWl + bRow * LDS + bCol);

#pragma unroll
    for (int kk = 0; kk < 8; kk++) {
        const uint32_t ko = kk * 32;           // kk*16 elements * 2B
        uint32_t aH[4][4], aL[4][4], bH[4][2], bL[4][2];
#pragma unroll
        for (int mi = 0; mi < 4; mi++) {
            ldsm_x4(aH[mi][0], aH[mi][1], aH[mi][2], aH[mi][3],
                    aHB + mi * (16 * LDS * 2) + ko);
            ldsm_x4(aL[mi][0], aL[mi][1], aL[mi][2], aL[mi][3],
                    aLB + mi * (16 * LDS * 2) + ko);
        }
#pragma unroll
        for (int bi = 0; bi < 2; bi++) {
            ldsm_x4(bH[2 * bi][0], bH[2 * bi][1], bH[2 * bi + 1][0], bH[2 * bi + 1][1],
                    bHB + bi * (16 * LDS * 2) + ko);
            ldsm_x4(bL[2 * bi][0], bL[2 * bi][1], bL[2 * bi + 1][0], bL[2 * bi + 1][1],
                    bLB + bi * (16 * LDS * 2) + ko);
        }
#pragma unroll
        for (int mi = 0; mi < 4; mi++)
#pragma unroll
            for (int ni = 0; ni < 4; ni++) {
                mma16816(acc[mi][ni], aH[mi], bH[ni]);
                mma16816(acc[mi][ni], aH[mi], bL[ni]);
                mma16816(acc[mi][ni], aL[mi], bH[ni]);
            }
    }

    // ---- epilogue: split-K partial [128 x 128] ----
    float* pb = g_part + ksl * (N_AG * OUTD);
    const int g2 = l >> 2, tig = l & 3;
#pragma unroll
    for (int mi = 0; mi < 4; mi++) {
        const int row = m0 + wm + mi * 16 + g2;
#pragma unroll
        for (int ni = 0; ni < 4; ni++) {
            const int col = wn + ni * 8 + tig * 2;
            *(float2*)(pb + row * OUTD + col)       = make_float2(acc[mi][ni][0], acc[mi][ni][1]);
            *(float2*)(pb + (row + 8) * OUTD + col) = make_float2(acc[mi][ni][2], acc[mi][ni][3]);
        }
    }
    // implicit launch_dependents at exit -> partials visible to biasrelu
}

// ===================== kernel 3: split-K reduce + bias + ReLU ================
__global__ void __launch_bounds__(256) biasrelu_kernel(const float* __restrict__ b,
                                                       float* __restrict__ out) {
    griddep_wait();
    const int idx = blockIdx.x * 256 + threadIdx.x;    // 32768 float4s
    float4 s = make_float4(0.f, 0.f, 0.f, 0.f);
#pragma unroll
    for (int ks = 0; ks < NKS; ks++) {
        float4 v = ((const float4*)(g_part + ks * (N_AG * OUTD)))[idx];
        s.x += v.x; s.y += v.y; s.z += v.z; s.w += v.w;
    }
    float4 bv = ((const float4*)b)[idx & 31];          // 32 float4 per row
    s.x = fmaxf(s.x + bv.x, 0.f);
    s.y = fmaxf(s.y + bv.y, 0.f);
    s.z = fmaxf(s.z + bv.z, 0.f);
    s.w = fmaxf(s.w + bv.w, 0.f);
    ((float4*)out)[idx] = s;
}

// =============================================================================
extern "C" void kernel_launch(void* const* d_in, const int* in_sizes, int n_in,
                              void* d_out, int out_size) {
    const float* hidden = (const float*)d_in[0];
    const float* obs2   = (const float*)d_in[2];
    const float* W      = (const float*)d_in[3];
    const float* b      = (const float*)d_in[4];
    float*       out    = (float*)d_out;

    cudaFuncSetAttribute(flatgemm_kernel, cudaFuncAttributeMaxDynamicSharedMemorySize, SMEM_DYN);

    scatter_kernel<<<N_AG, 256>>>(obs2);

    cudaLaunchAttribute attr[1];
    attr[0].id = cudaLaunchAttributeProgrammaticStreamSerialization;
    attr[0].val.programmaticStreamSerializationAllowed = 1;

    cudaLaunchConfig_t cfg = {};
    cfg.gridDim = dim3(N_AG / 128, NKS);   // (8, 16)
    cfg.blockDim = dim3(256);
    cfg.dynamicSmemBytes = SMEM_DYN;
    cfg.stream = 0;
    cfg.attrs = attr;
    cfg.numAttrs = 1;
    cudaLaunchKernelEx(&cfg, flatgemm_kernel, hidden, W);

    cfg.gridDim = dim3(N_AG * OUTD / 4 / 256);   // 128
    cfg.dynamicSmemBytes = 0;
    cudaLaunchKernelEx(&cfg, biasrelu_kernel, b, out);
}

// round 14
// speedup vs baseline: 1.5594x; 1.5594x over previous
#include <cuda_runtime.h>
#include <cuda_fp16.h>
#include <cstdint>

#define N_AG  1024
#define HID   128
#define KDIM  2048
#define OUTD  128
#define CELLS 1024

// ---- scratch (device globals; no allocs allowed) ----
__device__ __align__(16) __half g_Bh[KDIM * HID];    // Wperm hi (fp16)
__device__ __align__(16) __half g_Bls[KDIM * HID];   // Wperm lo * 2^11 (fp16)
__device__ float g_P[N_AG * KDIM];                   // 8 MB projections

__device__ __forceinline__ uint32_t smem_u32(const void* p) {
    uint32_t a;
    asm("{ .reg .u64 t; cvta.to.shared.u64 t, %1; cvt.u32.u64 %0, t; }" : "=r"(a) : "l"(p));
    return a;
}
__device__ __forceinline__ void griddep_wait() {
    asm volatile("griddepcontrol.wait;" ::: "memory");
}
__device__ __forceinline__ void griddep_launch() {
    asm volatile("griddepcontrol.launch_dependents;" ::: "memory");
}
__device__ __forceinline__ void ldsm_x4(uint32_t& r0, uint32_t& r1, uint32_t& r2, uint32_t& r3,
                                        uint32_t addr) {
    asm volatile("ldmatrix.sync.aligned.m8n8.x4.shared.b16 {%0,%1,%2,%3}, [%4];"
                 : "=r"(r0), "=r"(r1), "=r"(r2), "=r"(r3) : "r"(addr));
}
__device__ __forceinline__ void mma16816_f16(float* c, const uint32_t* a, const uint32_t* b) {
    asm volatile("mma.sync.aligned.m16n8k16.row.col.f32.f16.f16.f32 "
                 "{%0,%1,%2,%3}, {%4,%5,%6,%7}, {%8,%9}, {%0,%1,%2,%3};"
                 : "+f"(c[0]), "+f"(c[1]), "+f"(c[2]), "+f"(c[3])
                 : "r"(a[0]), "r"(a[1]), "r"(a[2]), "r"(a[3]), "r"(b[0]), "r"(b[1]));
}
__device__ __forceinline__ void cp_async16(uint32_t dst, const void* src) {
    asm volatile("cp.async.cg.shared.global [%0], [%1], 16;" :: "r"(dst), "l"(src) : "memory");
}

// ======================= prep kernel: convW only =============================
// 128 blocks: tiled transpose W[n][h*16+blk] -> Wperm[blk*128+n][h],
// fp16 split: Bh = fp16(v), Bls = fp16((v - Bh) * 2048).
#define NT 8       // n rows per tile
#define KT 256     // k cols per tile

__global__ void __launch_bounds__(256) prep_kernel(const float* __restrict__ W) {
    __shared__ float cw[NT][KT + 1];     // ~8.1 KB
    const int b0 = blockIdx.x;
    const int t  = threadIdx.x;   // 256

    griddep_launch();             // early-launch dependents (wait = completion)

    const int nt = b0 >> 3, kt = b0 & 7;
    const int n0 = nt * NT, k0 = kt * KT, h0 = kt * 16;
#pragma unroll
    for (int q = t; q < NT * KT / 4; q += 256) {   // 512 float4s, 2/thread
        int r = q >> 6, c4 = q & 63;
        float4 v = *(const float4*)(W + (n0 + r) * KDIM + k0 + c4 * 4);
        cw[r][c4 * 4 + 0] = v.x;
        cw[r][c4 * 4 + 1] = v.y;
        cw[r][c4 * 4 + 2] = v.z;
        cw[r][c4 * 4 + 3] = v.w;
    }
    __syncthreads();
    if (t < 128) {
        const int blk = t >> 3, nn = t & 7;
        const int r = (blk << 7) | (n0 + nn);
        __align__(16) __half hi[16];
        __align__(16) __half lo[16];
#pragma unroll
        for (int hr = 0; hr < 16; hr++) {
            float v = cw[nn][hr * 16 + blk];
            hi[hr] = __float2half_rn(v);
            lo[hr] = __float2half_rn((v - __half2float(hi[hr])) * 2048.0f);
        }
        *(uint4*)(g_Bh  + r * HID + h0)     = *(const uint4*)&hi[0];
        *(uint4*)(g_Bh  + r * HID + h0 + 8) = *(const uint4*)&hi[8];
        *(uint4*)(g_Bls + r * HID + h0)     = *(const uint4*)&lo[0];
        *(uint4*)(g_Bls + r * HID + h0 + 8) = *(const uint4*)&lo[8];
    }
}

// ============================ mma.sync GEMM ==================================
// P = hidden(1024x128) @ Wperm^T(2048x128). grid(8,16), 256 thr, 128x128 tile.
// 2 fp16 passes: acc = Ah*Bh, accLo = Ah*(Bl*2^11); P = acc + accLo/2048.
// Dropped Al*B term ~ 2^-11 relative (~1.5e-4) — under the 1e-3 threshold.
#define LDS   136
#define TILE  (128 * LDS)
#define SMEM_DYN (3 * TILE * 2)            // 104448 B

__global__ void __launch_bounds__(256, 1) gemm_mma_kernel(const float* __restrict__ Hs) {
    extern __shared__ __half sm[];
    __half* sAh = sm;
    __half* sBh = sm + TILE;
    __half* sBl = sm + 2 * TILE;

    const int t  = threadIdx.x;
    const int w  = t >> 5;
    const int l  = t & 31;
    const int m0 = blockIdx.x << 7;
    const int n0 = blockIdx.y << 7;
    const int wm = (w >> 2) * 64;
    const int wn = (w & 3) * 32;

    // ---- A convert: hidden fp32 -> fp16 hi in smem (no dependency) ----
#pragma unroll
    for (int q = t; q < 4096; q += 256) {  // 128 rows x 32 float4
        int r = q >> 5, c = q & 31;
        float4 v = *(const float4*)(Hs + (m0 + r) * HID + c * 4);
        __align__(8) __half hi[4];
        hi[0] = __float2half_rn(v.x);
        hi[1] = __float2half_rn(v.y);
        hi[2] = __float2half_rn(v.z);
        hi[3] = __float2half_rn(v.w);
        *(uint2*)(sAh + r * LDS + c * 4) = *(const uint2*)&hi[0];
    }

    griddep_launch();             // let out_kernel start its scatter
    griddep_wait();               // prep complete -> g_Bh/g_Bls visible

    // ---- B tiles from prep output ----
#pragma unroll
    for (int q = t; q < 2048; q += 256) {  // 16B chunks
        int r = q >> 4, c = q & 15;
        cp_async16(smem_u32(sBh + r * LDS + c * 8), g_Bh  + (n0 + r) * HID + c * 8);
        cp_async16(smem_u32(sBl + r * LDS + c * 8), g_Bls + (n0 + r) * HID + c * 8);
    }
    asm volatile("cp.async.commit_group;" ::: "memory");
    asm volatile("cp.async.wait_group 0;" ::: "memory");
    __syncthreads();

    float acc[4][4][4], accLo[4][4][4];
#pragma unroll
    for (int mi = 0; mi < 4; mi++)
#pragma unroll
        for (int ni = 0; ni < 4; ni++)
#pragma unroll
            for (int q = 0; q < 4; q++) { acc[mi][ni][q] = 0.0f; accLo[mi][ni][q] = 0.0f; }

    const int aRow = wm + (l & 15);
    const int aCol = (l >> 4) * 8;
    const int bRow = wn + ((l >> 4) * 8) + (l & 7);
    const int bCol = ((l >> 3) & 1) * 8;

    const uint32_t aHB = smem_u32(sAh + aRow * LDS + aCol);
    const uint32_t bHB = smem_u32(sBh + bRow * LDS + bCol);
    const uint32_t bLB = smem_u32(sBl + bRow * LDS + bCol);

#pragma unroll
    for (int kk = 0; kk < 8; kk++) {
        const uint32_t ko = kk * 32;       // kk*16 elements * 2B
        uint32_t aH[4][4], bH[4][2], bL[4][2];
#pragma unroll
        for (int mi = 0; mi < 4; mi++)
            ldsm_x4(aH[mi][0], aH[mi][1], aH[mi][2], aH[mi][3],
                    aHB + mi * (16 * LDS * 2) + ko);
#pragma unroll
        for (int bi = 0; bi < 2; bi++) {
            ldsm_x4(bH[2 * bi][0], bH[2 * bi][1], bH[2 * bi + 1][0], bH[2 * bi + 1][1],
                    bHB + bi * (16 * LDS * 2) + ko);
            ldsm_x4(bL[2 * bi][0], bL[2 * bi][1], bL[2 * bi + 1][0], bL[2 * bi + 1][1],
                    bLB + bi * (16 * LDS * 2) + ko);
        }
#pragma unroll
        for (int mi = 0; mi < 4; mi++)
#pragma unroll
            for (int ni = 0; ni < 4; ni++) {
                mma16816_f16(acc[mi][ni],   aH[mi], bH[ni]);
                mma16816_f16(accLo[mi][ni], aH[mi], bL[ni]);
            }
    }

    const float s = 1.0f / 2048.0f;
    const int g2 = l >> 2, tig = l & 3;
#pragma unroll
    for (int mi = 0; mi < 4; mi++) {
        const int row = m0 + wm + mi * 16 + g2;
#pragma unroll
        for (int ni = 0; ni < 4; ni++) {
            const int col = n0 + wn + ni * 8 + tig * 2;
            *(float2*)(g_P + row * KDIM + col) =
                make_float2(acc[mi][ni][0] + accLo[mi][ni][0] * s,
                            acc[mi][ni][1] + accLo[mi][ni][1] * s);
            *(float2*)(g_P + (row + 8) * KDIM + col) =
                make_float2(acc[mi][ni][2] + accLo[mi][ni][2] * s,
                            acc[mi][ni][3] + accLo[mi][ni][3] * s);
        }
    }
}

// ================= fused scatter + output gather =============================
// One CTA per ego. Scatter (obs2 only, overlaps GEMM via PDL early-launch),
// then griddepcontrol.wait (gemm complete), then gather P rows.
__global__ void __launch_bounds__(256) out_kernel(const float* __restrict__ obs2,
                                                  const float* __restrict__ b,
                                                  float* __restrict__ out) {
    __shared__ int    w[CELLS];
    __shared__ int    se[CELLS];
    __shared__ int    s_cnt;
    __shared__ float4 sp[8][32];
    const int i = blockIdx.x;
    const int t = threadIdx.x;     // 256
    const int g = t >> 5, l = t & 31;

    for (int c = t; c < CELLS; c += 256) w[c] = -1;
    if (t == 0) s_cnt = 0;
    const float2 oi = ((const float2*)obs2)[i];    // broadcast load
    __syncthreads();

    int cnt = 0;
    if (oi.x == oi.x) {                            // ego not NaN (uniform)
        for (int j = t; j < N_AG; j += 256) {      // obs2 L2-resident (8KB)
            if (j == i) continue;
            float2 oj = ((const float2*)obs2)[j];
            if (oj.x != oj.x) continue;            // neighbor NaN
            float ox = (oj.x - oi.x) * 4.0f + 16.0f;   // exact pow2 scale
            float oy = (oj.y - oi.y) * 4.0f + 16.0f;
            if (ox >= 0.0f && ox < 32.0f && oy >= 0.0f && oy < 32.0f)
                atomicMax(&w[((int)ox) * 32 + (int)oy], j);  // set-sem: max j
        }
        __syncthreads();
        for (int c = t; c < CELLS; c += 256) {
            int j = w[c];
            if (j >= 0) {
                int blk = ((c >> 8) << 2) | ((c & 31) >> 3);   // gi*4+gj
                int p = atomicAdd(&s_cnt, 1);
                se[p] = (j << 11) | (blk << 7);    // row offset into P
            }
        }
        __syncthreads();
        cnt = s_cnt;
    }

    griddep_wait();                                // gemm complete -> g_P visible

    float4 acc = make_float4(0.f, 0.f, 0.f, 0.f);
    for (int e = g; e < cnt; e += 8) {
        float4 v = *(const float4*)(g_P + se[e] + l * 4);
        acc.x += v.x; acc.y += v.y; acc.z += v.z; acc.w += v.w;
    }
    sp[g][l] = acc;
    __syncthreads();

    if (g == 0) {
        float4 s = sp[0][l];
#pragma unroll
        for (int q = 1; q < 8; q++) {
            float4 v = sp[q][l];
            s.x += v.x; s.y += v.y; s.z += v.z; s.w += v.w;
        }
        float4 bv = ((const float4*)b)[l];
        s.x = fmaxf(s.x + bv.x, 0.f);
        s.y = fmaxf(s.y + bv.y, 0.f);
        s.z = fmaxf(s.z + bv.z, 0.f);
        s.w = fmaxf(s.w + bv.w, 0.f);
        ((float4*)(out + i * OUTD))[l] = s;
    }
}

// =============================================================================
extern "C" void kernel_launch(void* const* d_in, const int* in_sizes, int n_in,
                              void* d_out, int out_size) {
    const float* hidden = (const float*)d_in[0];
    const float* obs2   = (const float*)d_in[2];
    const float* W      = (const float*)d_in[3];
    const float* b      = (const float*)d_in[4];
    float*       out    = (float*)d_out;

    cudaFuncSetAttribute(gemm_mma_kernel, cudaFuncAttributeMaxDynamicSharedMemorySize, SMEM_DYN);

    prep_kernel<<<128, 256>>>(W);

    cudaLaunchAttribute attr[1];
    attr[0].id = cudaLaunchAttributeProgrammaticStreamSerialization;
    attr[0].val.programmaticStreamSerializationAllowed = 1;

    cudaLaunchConfig_t cfg = {};
    cfg.gridDim = dim3(N_AG / 128, KDIM / 128);   // (8, 16)
    cfg.blockDim = dim3(256);
    cfg.dynamicSmemBytes = SMEM_DYN;
    cfg.stream = 0;
    cfg.attrs = attr;
    cfg.numAttrs = 1;
    cudaLaunchKernelEx(&cfg, gemm_mma_kernel, hidden);

    cfg.gridDim = dim3(N_AG);
    cfg.dynamicSmemBytes = 0;
    cudaLaunchKernelEx(&cfg, out_kernel, obs2, b, out);
}